// round 15
// baseline (speedup 1.0000x reference)
#include <cuda_runtime.h>
#include <cuda_fp16.h>
#include <cstdint>

#define Hh 8
#define Bn 16
#define Ls 1024
#define Dm 512
#define M_ALL (Bn*Ls)              /* 16384 */
#define OUT_ELEMS (Bn*Ls*Dm)       /* 8388608 */
#define NROWS (Hh*Bn*Ls)           /* 131072 */
#define CCH  9.728829e-7f          /* (1/sqrt(512))*log2(e)/65536 */
#define UNSC 1.52587890625e-5f     /* 2^-16 */

// ---------------- static device scratch (packed-pair u32 = 2 b16, consec k) --
__device__ uint32_t g_q  [M_ALL*512];   // Q proj, fp16 x256; head h: hi [h*64..+32), lo [+32..+64)
__device__ uint32_t g_k  [M_ALL*512];
__device__ float    g_vs [M_ALL*Dm];    // V proj fp32
__device__ uint32_t g_ho [M_ALL*512];   // headout bf16: hi [0,256), lo [256,512)
__device__ uint32_t g_po [M_ALL*512];   // projout bf16
__device__ uint32_t g_qd [M_ALL*512];   // q_data bf16 (lin A1)
__device__ uint32_t g_qdh[M_ALL*512];   // q_data fp16 x256 (Q proj A)
__device__ uint32_t g_kdh[M_ALL*512];   // k_data fp16 x256
__device__ uint32_t g_vdb[M_ALL*512];   // v_data bf16
__device__ uint32_t g_wqt[512*512];     // wq^T fp16 x256: [n=h*64+e][hi 256 | lo 256]
__device__ uint32_t g_wkt[512*512];
__device__ uint32_t g_wvt[512*512];     // bf16
__device__ uint32_t g_pw [512*512];     // proj_w bf16 [n][hi 256|lo 256]
__device__ uint32_t g_lw [512*1024];    // lin_w bf16 [n][hi 512|lo 512]

// ---------------- helpers ----------------
__device__ __forceinline__ uint32_t smem_u32(const void* p) {
    uint32_t a;
    asm("{ .reg .u64 t; cvta.to.shared.u64 t, %1; cvt.u32.u64 %0, t; }" : "=r"(a) : "l"(p));
    return a;
}
__device__ __forceinline__ void cp_async16(void* sdst, const void* gsrc) {
    uint32_t s = smem_u32(sdst);
    asm volatile("cp.async.ca.shared.global [%0], [%1], 16;" :: "r"(s), "l"(gsrc));
}
#define CP_COMMIT() asm volatile("cp.async.commit_group;" ::: "memory")
#define CP_WAIT1()  asm volatile("cp.async.wait_group 1;" ::: "memory")
#define CP_WAIT0()  asm volatile("cp.async.wait_group 0;" ::: "memory")

__device__ __forceinline__ void split2(float x0, float x1, uint32_t& hi, uint32_t& lo) {
    uint32_t h;
    asm("cvt.rn.bf16x2.f32 %0, %1, %2;" : "=r"(h) : "f"(x1), "f"(x0));
    float h0 = __uint_as_float(h << 16);
    float h1 = __uint_as_float(h & 0xffff0000u);
    float r0 = x0 - h0, r1 = x1 - h1;
    asm("cvt.rn.bf16x2.f32 %0, %1, %2;" : "=r"(lo) : "f"(r1), "f"(r0));
    hi = h;
}
__device__ __forceinline__ void split2h(float x0, float x1, uint32_t& hi, uint32_t& lo) {
    x0 *= 256.f; x1 *= 256.f;
    __half2 h = __floats2half2_rn(x0, x1);
    float f0 = __half2float(__low2half(h));
    float f1 = __half2float(__high2half(h));
    __half2 l = __floats2half2_rn(x0 - f0, x1 - f1);
    hi = *(uint32_t*)&h;
    lo = *(uint32_t*)&l;
}
__device__ __forceinline__ void mma16(float* d, const uint32_t* a, const uint32_t* b) {
    asm volatile("mma.sync.aligned.m16n8k16.row.col.f32.bf16.bf16.f32 "
                 "{%0,%1,%2,%3}, {%4,%5,%6,%7}, {%8,%9}, {%0,%1,%2,%3};"
                 : "+f"(d[0]), "+f"(d[1]), "+f"(d[2]), "+f"(d[3])
                 : "r"(a[0]), "r"(a[1]), "r"(a[2]), "r"(a[3]),
                   "r"(b[0]), "r"(b[1]));
}
__device__ __forceinline__ void mma16h(float* d, const uint32_t* a, const uint32_t* b) {
    asm volatile("mma.sync.aligned.m16n8k16.row.col.f32.f16.f16.f32 "
                 "{%0,%1,%2,%3}, {%4,%5,%6,%7}, {%8,%9}, {%0,%1,%2,%3};"
                 : "+f"(d[0]), "+f"(d[1]), "+f"(d[2]), "+f"(d[3])
                 : "r"(a[0]), "r"(a[1]), "r"(a[2]), "r"(a[3]),
                   "r"(b[0]), "r"(b[1]));
}
__device__ __forceinline__ void ldsm4(uint32_t* r, uint32_t a) {
    asm volatile("ldmatrix.sync.aligned.m8n8.x4.shared.b16 {%0,%1,%2,%3}, [%4];"
                 : "=r"(r[0]), "=r"(r[1]), "=r"(r[2]), "=r"(r[3]) : "r"(a));
}
__device__ __forceinline__ float fex2(float z) {
    float r;
    asm("ex2.approx.f32 %0, %1;" : "=f"(r) : "f"(z));
    return r;
}

#define ACC_INIT() float acc[4][4][4];                                           \
    _Pragma("unroll") for (int a_ = 0; a_ < 4; a_++)                             \
    _Pragma("unroll") for (int b_ = 0; b_ < 4; b_++)                             \
    _Pragma("unroll") for (int c_ = 0; c_ < 4; c_++) acc[a_][b_][c_] = 0.f;

// ============================================================================
// prep: split activations + weights into packed-pair arrays (single launch)
// ============================================================================
#define PREP_ACT_N (3*M_ALL*128)
__global__ void prep_all(const float* __restrict__ qd, const float* __restrict__ kd,
                         const float* __restrict__ vd,
                         const float* __restrict__ wq, const float* __restrict__ wk,
                         const float* __restrict__ wv, const float* __restrict__ pw,
                         const float* __restrict__ lw)
{
    int idx = blockIdx.x * 256 + threadIdx.x;
    uint32_t h0, l0, h1, l1;
    if (idx < PREP_ACT_N) {
        int which = idx / (M_ALL * 128);
        int r = idx - which * (M_ALL * 128);
        int m = r >> 7, f = r & 127;
        if (which == 0) {
            float4 v = *(const float4*)(qd + (size_t)m * 512 + f * 4);
            split2h(v.x, v.y, h0, l0); split2h(v.z, v.w, h1, l1);
            *(uint2*)(g_qdh + (size_t)m * 512 + 2 * f)       = make_uint2(h0, h1);
            *(uint2*)(g_qdh + (size_t)m * 512 + 256 + 2 * f) = make_uint2(l0, l1);
            split2(v.x, v.y, h0, l0); split2(v.z, v.w, h1, l1);
            *(uint2*)(g_qd + (size_t)m * 512 + 2 * f)       = make_uint2(h0, h1);
            *(uint2*)(g_qd + (size_t)m * 512 + 256 + 2 * f) = make_uint2(l0, l1);
        } else if (which == 1) {
            float4 v = *(const float4*)(kd + (size_t)m * 512 + f * 4);
            split2h(v.x, v.y, h0, l0); split2h(v.z, v.w, h1, l1);
            *(uint2*)(g_kdh + (size_t)m * 512 + 2 * f)       = make_uint2(h0, h1);
            *(uint2*)(g_kdh + (size_t)m * 512 + 256 + 2 * f) = make_uint2(l0, l1);
        } else {
            float4 v = *(const float4*)(vd + (size_t)m * 512 + f * 4);
            split2(v.x, v.y, h0, l0); split2(v.z, v.w, h1, l1);
            *(uint2*)(g_vdb + (size_t)m * 512 + 2 * f)       = make_uint2(h0, h1);
            *(uint2*)(g_vdb + (size_t)m * 512 + 256 + 2 * f) = make_uint2(l0, l1);
        }
        return;
    }
    idx -= PREP_ACT_N;
    if (idx < 3 * 8 * 256 * 64) {                    // qkv weights, transposed split
        int e = idx & 63;
        int p = (idx >> 6) & 255;
        int h = (idx >> 14) & 7;
        int z = idx >> 17;
        const float* W = ((z == 0) ? wq : (z == 1) ? wk : wv) + (size_t)h * 512 * 64;
        float x0 = W[(size_t)(2 * p) * 64 + e];
        float x1 = W[(size_t)(2 * p + 1) * 64 + e];
        int n = h * 64 + e;
        uint32_t hi, lo;
        if (z == 2) {
            split2(x0, x1, hi, lo);
            g_wvt[(size_t)n * 512 + p] = hi; g_wvt[(size_t)n * 512 + 256 + p] = lo;
        } else {
            split2h(x0, x1, hi, lo);
            uint32_t* dst = (z == 0) ? g_wqt : g_wkt;
            dst[(size_t)n * 512 + p] = hi; dst[(size_t)n * 512 + 256 + p] = lo;
        }
        return;
    }
    idx -= 3 * 8 * 256 * 64;
    if (idx < 512 * 128) {                           // proj_w
        int n = idx >> 7, f = idx & 127;
        float4 v = *(const float4*)(pw + (size_t)n * 512 + f * 4);
        split2(v.x, v.y, h0, l0); split2(v.z, v.w, h1, l1);
        *(uint2*)(g_pw + (size_t)n * 512 + 2 * f)       = make_uint2(h0, h1);
        *(uint2*)(g_pw + (size_t)n * 512 + 256 + 2 * f) = make_uint2(l0, l1);
        return;
    }
    idx -= 512 * 128;
    if (idx < 512 * 256) {                           // lin_w
        int n = idx >> 8, f = idx & 255;
        float4 v = *(const float4*)(lw + (size_t)n * 1024 + f * 4);
        split2(v.x, v.y, h0, l0); split2(v.z, v.w, h1, l1);
        *(uint2*)(g_lw + (size_t)n * 1024 + 2 * f)       = make_uint2(h0, h1);
        *(uint2*)(g_lw + (size_t)n * 1024 + 512 + 2 * f) = make_uint2(l0, l1);
    }
}
#define PREP_TOTAL (PREP_ACT_N + 3*8*256*64 + 512*128 + 512*256)

// ============================================================================
// Unified pre-split GEMM core: pure ldmatrix+HMMA. 128x64 CTA tile, 4 warps
// 2(M)x2(N), warp tile 64x32, chunks of 16 pairs (k=32).
// 3-STAGE cp.async pipeline, ONE __syncthreads per chunk (loads issued
// before compute; buffer (c+2)%3 was last read in compute(c-1), which all
// warps finished before this iteration's barrier). 2 CTAs/SM.
// EPI: 0 = packed fp16 x256, 1 = fp32, 2 = packed bf16 + bias, 3 = fp32 + bias
// ============================================================================
#define PKPAD 36
#define PK_SMEM (3*(128*PKPAD + 64*PKPAD)*4)   /* 82944 */

template<bool FP16, int EPI>
__device__ __forceinline__ void pk_core(
    const uint32_t* __restrict__ A1, const uint32_t* __restrict__ A2, int K1p, int Kp,
    const uint32_t* __restrict__ Bm, int ldb,
    const float* __restrict__ bias, float* __restrict__ Cf, uint32_t* __restrict__ Cp,
    int m0, int n0, uint32_t* smu)
{
    uint32_t* Abuf[3] = { smu, smu + 192*PKPAD, smu + 384*PKPAD };
    uint32_t* Bbuf[3] = { smu + 128*PKPAD, smu + 192*PKPAD + 128*PKPAD,
                          smu + 384*PKPAD + 128*PKPAD };
    const int tid = threadIdx.x;
    const int wid = tid >> 5, lane = tid & 31;
    const int wm = wid & 1, wn = wid >> 1;
    const int lr = lane >> 2, lc = lane & 3;
    const int NC = Kp / 16;
    const int lob = ldb >> 1;

    const int a_off = ((lane&7) + ((lane>>3)&1)*8)*PKPAD + (lane>>4)*4;
    const int b_off = (lane&7)*PKPAD + ((lane>>3)&1)*4 + (lane>>4)*16;
    uint32_t a_sh[3], b_sh[3];
#pragma unroll
    for (int s = 0; s < 3; s++) {
        a_sh[s] = smem_u32(Abuf[s]) + (wm*64*PKPAD + a_off)*4;
        b_sh[s] = smem_u32(Bbuf[s]) + (wn*32*PKPAD + b_off)*4;
    }

#define A_LOADP(buf, c_) do {                                                     \
        int p0_; const uint32_t* Asrc;                                            \
        if ((c_)*16 < K1p) { Asrc = A1; p0_ = (c_)*16; }                          \
        else               { Asrc = A2; p0_ = (c_)*16 - K1p; }                    \
        _Pragma("unroll")                                                         \
        for (int i = 0; i < 4; i++) {                                             \
            int id = tid + i * 128;                                               \
            int row = id >> 2, seg = (id & 3) * 4;                                \
            cp_async16(Abuf[buf] + row*PKPAD + seg,                               \
                       Asrc + (size_t)(m0 + row)*512 + p0_ + seg);                \
        }                                                                          \
        _Pragma("unroll")                                                         \
        for (int i = 0; i < 4; i++) {                                             \
            int id = tid + i * 128;                                               \
            int row = id >> 2, seg = (id & 3) * 4;                                \
            cp_async16(Abuf[buf] + row*PKPAD + 16 + seg,                          \
                       Asrc + (size_t)(m0 + row)*512 + 256 + p0_ + seg);          \
        }                                                                          \
    } while (0)
#define B_LOADP(buf, c_) do {                                                     \
        int p0_ = (c_) * 16;                                                      \
        _Pragma("unroll")                                                         \
        for (int i = 0; i < 2; i++) {                                             \
            int id = tid + i * 128;                                               \
            int row = id >> 2, seg = (id & 3) * 4;                                \
            cp_async16(Bbuf[buf] + row*PKPAD + seg,                               \
                       Bm + (size_t)(n0 + row)*ldb + p0_ + seg);                  \
        }                                                                          \
        _Pragma("unroll")                                                         \
        for (int i = 0; i < 2; i++) {                                             \
            int id = tid + i * 128;                                               \
            int row = id >> 2, seg = (id & 3) * 4;                                \
            cp_async16(Bbuf[buf] + row*PKPAD + 16 + seg,                          \
                       Bm + (size_t)(n0 + row)*ldb + lob + p0_ + seg);            \
        }                                                                          \
    } while (0)

    A_LOADP(0, 0); B_LOADP(0, 0); CP_COMMIT();
    A_LOADP(1, 1); B_LOADP(1, 1); CP_COMMIT();
    ACC_INIT()

    int buf = 0;                    // = c % 3
    for (int c = 0; c < NC; c++) {
        CP_WAIT1();                 // chunk c complete (c+1 may be in flight)
        __syncthreads();            // visibility + all warps done with compute(c-1)
        if (c + 2 < NC) {
            int nb = buf + 2; if (nb >= 3) nb -= 3;     // (c+2)%3 == (c-1)%3
            A_LOADP(nb, c + 2); B_LOADP(nb, c + 2); CP_COMMIT();
        }
#pragma unroll
        for (int ks = 0; ks < 2; ks++) {
            uint32_t bfr[4][4];
#pragma unroll
            for (int nt = 0; nt < 4; nt++)
                ldsm4(bfr[nt], b_sh[buf] + (nt*8*PKPAD + ks*8)*4);
#pragma unroll
            for (int mt = 0; mt < 4; mt++) {
                uint32_t ah[4], al[4];
                uint32_t aa = a_sh[buf] + (mt*16*PKPAD + ks*8)*4;
                ldsm4(ah, aa);
                ldsm4(al, aa + 64);
#pragma unroll
                for (int nt = 0; nt < 4; nt++) {
                    if (FP16) {
                        mma16h(acc[mt][nt], ah, bfr[nt]);
                        mma16h(acc[mt][nt], ah, bfr[nt] + 2);
                        mma16h(acc[mt][nt], al, bfr[nt]);
                    } else {
                        mma16(acc[mt][nt], ah, bfr[nt]);
                        mma16(acc[mt][nt], ah, bfr[nt] + 2);
                        mma16(acc[mt][nt], al, bfr[nt]);
                    }
                }
            }
        }
        if (++buf == 3) buf = 0;
    }

#pragma unroll
    for (int mt = 0; mt < 4; mt++) {
#pragma unroll
        for (int nt = 0; nt < 4; nt++) {
            int row = m0 + wm*64 + mt*16 + lr;
            if (EPI == 0) {
                int colp = wn*16 + nt*4 + lc;
                uint32_t hi, lo;
                split2h(acc[mt][nt][0]*UNSC, acc[mt][nt][1]*UNSC, hi, lo);
                Cp[(size_t)row*512 + n0 + colp]      = hi;
                Cp[(size_t)row*512 + n0 + 32 + colp] = lo;
                split2h(acc[mt][nt][2]*UNSC, acc[mt][nt][3]*UNSC, hi, lo);
                Cp[(size_t)(row+8)*512 + n0 + colp]      = hi;
                Cp[(size_t)(row+8)*512 + n0 + 32 + colp] = lo;
            } else if (EPI == 1) {
                int col = n0 + wn*32 + nt*8 + 2*lc;
                *(float2*)(Cf + (size_t)row * Dm + col) =
                    make_float2(acc[mt][nt][0], acc[mt][nt][1]);
                *(float2*)(Cf + (size_t)(row + 8) * Dm + col) =
                    make_float2(acc[mt][nt][2], acc[mt][nt][3]);
            } else if (EPI == 2) {
                int col = n0 + wn*32 + nt*8 + 2*lc;
                float bx = bias[col], by = bias[col + 1];
                int pair = col >> 1;
                uint32_t hi, lo;
                split2(acc[mt][nt][0] + bx, acc[mt][nt][1] + by, hi, lo);
                Cp[(size_t)row*512 + pair] = hi;
                Cp[(size_t)row*512 + 256 + pair] = lo;
                split2(acc[mt][nt][2] + bx, acc[mt][nt][3] + by, hi, lo);
                Cp[(size_t)(row+8)*512 + pair] = hi;
                Cp[(size_t)(row+8)*512 + 256 + pair] = lo;
            } else {
                int col = n0 + wn*32 + nt*8 + 2*lc;
                float bx = bias[col], by = bias[col + 1];
                *(float2*)(Cf + (size_t)row * Dm + col) =
                    make_float2(acc[mt][nt][0] + bx, acc[mt][nt][1] + by);
                *(float2*)(Cf + (size_t)(row + 8) * Dm + col) =
                    make_float2(acc[mt][nt][2] + bx, acc[mt][nt][3] + by);
            }
        }
    }
#undef A_LOADP
#undef B_LOADP
}

__global__ __launch_bounds__(128, 2) void qkv_pk()
{
    extern __shared__ uint32_t smu[];
    const int z = blockIdx.z;
    const int m0 = blockIdx.y * 128, n0 = blockIdx.x * 64;
    if (z == 0)
        pk_core<true, 0>(g_qdh, g_qdh, 256, 256, g_wqt, 512, nullptr, nullptr, g_q, m0, n0, smu);
    else if (z == 1)
        pk_core<true, 0>(g_kdh, g_kdh, 256, 256, g_wkt, 512, nullptr, nullptr, g_k, m0, n0, smu);
    else
        pk_core<false, 1>(g_vdb, g_vdb, 256, 256, g_wvt, 512, nullptr, g_vs, nullptr, m0, n0, smu);
}

__global__ __launch_bounds__(128, 2) void proj_pk(const float* __restrict__ bias)
{
    extern __shared__ uint32_t smu[];
    pk_core<false, 2>(g_ho, g_ho, 256, 256, g_pw, 512, bias, nullptr, g_po,
                      blockIdx.y * 128, blockIdx.x * 64, smu);
}

__global__ __launch_bounds__(128, 2) void lin_pk(const float* __restrict__ bias,
                                                 float* __restrict__ out)
{
    extern __shared__ uint32_t smu[];
    pk_core<false, 3>(g_qd, g_po, 256, 512, g_lw, 1024, bias, out, nullptr,
                      blockIdx.y * 128, blockIdx.x * 64, smu);
}

// ============================================================================
// QK^T (ldmatrix + fp16 HMMA) + softmax stats + dense attn fill + coalesced
// fused V-gather. CTA = (h, b, 128 q rows). (unchanged from R14)
// ============================================================================
#define APADU 68
#define S_SMEM ((128*APADU + 2*64*APADU)*4 + 256*4*3 + 128*4*2)  /* 73728 */
__global__ __launch_bounds__(128, 3) void attn_stats_mma(float* __restrict__ attn)
{
    extern __shared__ uint32_t smu[];
    uint32_t* Qs = smu;
    uint32_t* Kbuf[2] = { smu + 128*APADU, smu + 128*APADU + 64*APADU };
    float* redm = (float*)(smu + 128*APADU + 2*64*APADU);
    float* reds = redm + 256;
    int*   redi = (int*)(reds + 256);
    float* pbuf = (float*)(redi + 256);
    int*   ibuf = (int*)(pbuf + 128);

    const int tid = threadIdx.x;
    const int h = blockIdx.z, b = blockIdx.y, q0 = blockIdx.x * 128;
    const int wid = tid >> 5, lane = tid & 31;
    const int wm = wid & 1, wn = wid >> 1;
    const int lr = lane >> 2, lc = lane & 3;

    const uint32_t* Qg = g_q + ((size_t)(b * Ls + q0)) * 512 + h * 64;
    const uint32_t* Kg = g_k + ((size_t)(b * Ls)) * 512 + h * 64;
    const size_t rowbase = (size_t)(h * Bn + b) * Ls + q0;

    const int a_off = ((lane&7) + ((lane>>3)&1)*8)*APADU + (lane>>4)*4;
    const int b_off = (lane&7)*APADU + ((lane>>3)&1)*4 + (lane>>4)*32;
    const uint32_t qs_sh = smem_u32(Qs) + (wm*64*APADU + a_off)*4;
    uint32_t k_sh[2];
    k_sh[0] = smem_u32(Kbuf[0]) + (wn*32*APADU + b_off)*4;
    k_sh[1] = smem_u32(Kbuf[1]) + (wn*32*APADU + b_off)*4;

#pragma unroll
    for (int i = 0; i < 16; i++) {
        int id = tid + i * 128;
        int row = id >> 4, seg = (id & 15) * 4;
        cp_async16(Qs + row*APADU + seg, Qg + (size_t)row * 512 + seg);
    }
    CP_COMMIT();

#define K_LOAD(buf, t_) do {                                                    \
        _Pragma("unroll")                                                       \
        for (int i = 0; i < 8; i++) {                                           \
            int id = tid + i * 128;                                             \
            int row = id >> 4, seg = (id & 15) * 4;                             \
            cp_async16(Kbuf[buf] + row*APADU + seg,                             \
                       Kg + (size_t)((t_)*64 + row) * 512 + seg);               \
        }                                                                       \
    } while (0)

    K_LOAD(0, 0); CP_COMMIT();
    K_LOAD(1, 1); CP_COMMIT();

    float rm[8], rs[8];
    int ridx[8];
#pragma unroll
    for (int i = 0; i < 8; i++) { rm[i] = -1e30f; rs[i] = 0.f; ridx[i] = 0; }

    for (int t = 0; t < 16; t++) {
        if (t < 15) CP_WAIT1(); else CP_WAIT0();
        __syncthreads();
        const int buf = t & 1;

        ACC_INIT()

#pragma unroll
        for (int ks = 0; ks < 4; ks++) {
            uint32_t bfr[4][4];
#pragma unroll
            for (int nt = 0; nt < 4; nt++)
                ldsm4(bfr[nt], k_sh[buf] + (nt*8*APADU + ks*8)*4);
#pragma unroll
            for (int mt = 0; mt < 4; mt++) {
                uint32_t ah[4], al[4];
                uint32_t aa = qs_sh + (mt*16*APADU + ks*8)*4;
                ldsm4(ah, aa);
                ldsm4(al, aa + 128);
#pragma unroll
                for (int nt = 0; nt < 4; nt++) {
                    mma16h(acc[mt][nt], ah, bfr[nt]);
                    mma16h(acc[mt][nt], ah, bfr[nt] + 2);
                    mma16h(acc[mt][nt], al, bfr[nt]);
                }
            }
        }

        // streaming zero-fill of this CTA's attn slice, s-range [t*64, t*64+64)
        {
            float4 z4 = make_float4(0.f, 0.f, 0.f, 0.f);
#pragma unroll
            for (int i = 0; i < 16; i++) {
                int id = tid + i * 128;
                int r = id >> 4, f4 = id & 15;
                __stcs((float4*)(attn + (rowbase + r) * Ls + t * 64 + f4 * 4), z4);
            }
        }

        // fold tile into per-thread stats
        const int sbase = t * 64 + wn * 32 + 2 * lc;
#pragma unroll
        for (int mt = 0; mt < 4; mt++) {
#pragma unroll
            for (int half = 0; half < 2; half++) {
                const int r8 = mt * 2 + half;
                float m = rm[r8], s_ = rs[r8];
                int id_ = ridx[r8];
#pragma unroll
                for (int nt = 0; nt < 4; nt++) {
#pragma unroll
                    for (int j = 0; j < 2; j++) {
                        float v = acc[mt][nt][half*2 + j];
                        if (v > m) { m = v; id_ = sbase + nt*8 + j; }
                        s_ += fex2(v * CCH);
                    }
                }
                rm[r8] = m; rs[r8] = s_; ridx[r8] = id_;
            }
        }
        __syncthreads();
        if (t + 2 < 16) { K_LOAD(buf, t + 2); CP_COMMIT(); }
    }

    // quad reduce over lc
#pragma unroll
    for (int r8 = 0; r8 < 8; r8++) {
        float m = rm[r8], s_ = rs[r8];
        int id_ = ridx[r8];
#pragma unroll
        for (int off = 1; off <= 2; off <<= 1) {
            float om = __shfl_xor_sync(0xffffffffu, m, off);
            float os = __shfl_xor_sync(0xffffffffu, s_, off);
            int   oi = __shfl_xor_sync(0xffffffffu, id_, off);
            s_ += os;
            if (om > m) { m = om; id_ = oi; }
        }
        if (lc == 0) {
            int rowl = wm*64 + (r8 >> 1)*16 + (r8 & 1)*8 + lr;
            redm[rowl*2 + wn] = m;
            reds[rowl*2 + wn] = s_;
            redi[rowl*2 + wn] = id_;
        }
    }
    __syncthreads();

    {
        float m = redm[tid*2], s_ = reds[tid*2];
        int id_ = redi[tid*2];
        float om = redm[tid*2 + 1];
        s_ += reds[tid*2 + 1];
        if (om > m) { m = om; id_ = redi[tid*2 + 1]; }
        float p = fex2(m * CCH) / s_;
        attn[(rowbase + tid) * Ls + id_] = p;
        pbuf[tid] = p;
        ibuf[tid] = id_;
    }
    __syncthreads();

    // coalesced fused V-gather
#pragma unroll
    for (int i = 0; i < 16; i++) {
        int id = tid + i * 128;
        int r  = id >> 4, e4 = id & 15;
        float p2 = pbuf[r];
        int   s2 = ibuf[r];
        float4 v = *(const float4*)(g_vs + ((size_t)(b * Ls + s2)) * Dm + h * 64 + e4 * 4);
        uint32_t h0, l0, h1, l1;
        split2(v.x * p2, v.y * p2, h0, l0);
        split2(v.z * p2, v.w * p2, h1, l1);
        uint32_t* ho = g_ho + (size_t)(b * Ls + q0 + r) * 512;
        int pairbase = h * 32 + e4 * 2;
        *(uint2*)(ho + pairbase)       = make_uint2(h0, h1);
        *(uint2*)(ho + 256 + pairbase) = make_uint2(l0, l1);
    }
#undef K_LOAD
}

// ============================================================================
extern "C" void kernel_launch(void* const* d_in, const int* in_sizes, int n_in,
                              void* d_out, int out_size)
{
    const float* q_data = (const float*)d_in[0];
    const float* k_data = (const float*)d_in[1];
    const float* v_data = (const float*)d_in[2];
    const float* w_qs   = (const float*)d_in[3];
    const float* w_ks   = (const float*)d_in[4];
    const float* w_vs   = (const float*)d_in[5];
    const float* proj_w = (const float*)d_in[6];
    const float* proj_b = (const float*)d_in[7];
    const float* lin_w  = (const float*)d_in[8];
    const float* lin_b  = (const float*)d_in[9];

    float* out  = (float*)d_out;                    // [B, L, D]
    float* attn = out + OUT_ELEMS;                  // [H*B, L, L]

    cudaFuncSetAttribute(qkv_pk,  cudaFuncAttributeMaxDynamicSharedMemorySize, PK_SMEM);
    cudaFuncSetAttribute(proj_pk, cudaFuncAttributeMaxDynamicSharedMemorySize, PK_SMEM);
    cudaFuncSetAttribute(lin_pk,  cudaFuncAttributeMaxDynamicSharedMemorySize, PK_SMEM);
    cudaFuncSetAttribute(attn_stats_mma, cudaFuncAttributeMaxDynamicSharedMemorySize, S_SMEM);

    // 0) pre-split all MMA inputs (single launch)
    prep_all<<<(PREP_TOTAL + 255) / 256, 256>>>(q_data, k_data, v_data,
                                                w_qs, w_ks, w_vs, proj_w, lin_w);

    // 1) Q/K/V projections (3-stage pipeline, 1 sync/chunk)
    qkv_pk<<<dim3(8, 128, 3), 128, PK_SMEM>>>();

    // 2) QK^T + softmax stats + dense attn fill + fused V-gather
    attn_stats_mma<<<dim3(8, 16, 8), 128, S_SMEM>>>(attn);

    // 3) output projection -> packed bf16 projout
    proj_pk<<<dim3(8, 128), 128, PK_SMEM>>>(proj_b);

    // 4) final linear: out = [q_data | projout] @ lin_w^T + lin_b
    lin_pk<<<dim3(8, 128), 128, PK_SMEM>>>(lin_b, out);
}

// round 16
// speedup vs baseline: 1.0611x; 1.0611x over previous
#include <cuda_runtime.h>
#include <cuda_fp16.h>
#include <cstdint>

#define Hh 8
#define Bn 16
#define Ls 1024
#define Dm 512
#define M_ALL (Bn*Ls)              /* 16384 */
#define OUT_ELEMS (Bn*Ls*Dm)       /* 8388608 */
#define NROWS (Hh*Bn*Ls)           /* 131072 */
#define CCH  9.728829e-7f          /* (1/sqrt(512))*log2(e)/65536 */
#define UNSC 1.52587890625e-5f     /* 2^-16 */

// ---------------- static device scratch (packed-pair u32 = 2 b16, consec k) --
__device__ uint32_t g_q  [M_ALL*512];   // Q proj, fp16 x256; head h: hi [h*64..+32), lo [+32..+64)
__device__ uint32_t g_k  [M_ALL*512];
__device__ float    g_vs [M_ALL*Dm];    // V proj fp32
__device__ uint32_t g_ho [M_ALL*512];   // headout bf16: hi [0,256), lo [256,512)
__device__ uint32_t g_po [M_ALL*512];   // projout bf16
__device__ uint32_t g_qd [M_ALL*512];   // q_data bf16 (lin A1)
__device__ uint32_t g_qdh[M_ALL*512];   // q_data fp16 x256 (Q proj A)
__device__ uint32_t g_kdh[M_ALL*512];   // k_data fp16 x256
__device__ uint32_t g_vdb[M_ALL*512];   // v_data bf16
__device__ uint32_t g_wqt[512*512];     // wq^T fp16 x256: [n=h*64+e][hi 256 | lo 256]
__device__ uint32_t g_wkt[512*512];
__device__ uint32_t g_wvt[512*512];     // bf16
__device__ uint32_t g_pw [512*512];     // proj_w bf16 [n][hi 256|lo 256]
__device__ uint32_t g_lw [512*1024];    // lin_w bf16 [n][hi 512|lo 512]
__device__ float g_p[NROWS];
__device__ int   g_amax[NROWS];

// ---------------- helpers ----------------
__device__ __forceinline__ uint32_t smem_u32(const void* p) {
    uint32_t a;
    asm("{ .reg .u64 t; cvta.to.shared.u64 t, %1; cvt.u32.u64 %0, t; }" : "=r"(a) : "l"(p));
    return a;
}
__device__ __forceinline__ void cp_async16(void* sdst, const void* gsrc) {
    uint32_t s = smem_u32(sdst);
    asm volatile("cp.async.ca.shared.global [%0], [%1], 16;" :: "r"(s), "l"(gsrc));
}
#define CP_COMMIT() asm volatile("cp.async.commit_group;" ::: "memory")
#define CP_WAIT1()  asm volatile("cp.async.wait_group 1;" ::: "memory")
#define CP_WAIT0()  asm volatile("cp.async.wait_group 0;" ::: "memory")

__device__ __forceinline__ void split2(float x0, float x1, uint32_t& hi, uint32_t& lo) {
    uint32_t h;
    asm("cvt.rn.bf16x2.f32 %0, %1, %2;" : "=r"(h) : "f"(x1), "f"(x0));
    float h0 = __uint_as_float(h << 16);
    float h1 = __uint_as_float(h & 0xffff0000u);
    float r0 = x0 - h0, r1 = x1 - h1;
    asm("cvt.rn.bf16x2.f32 %0, %1, %2;" : "=r"(lo) : "f"(r1), "f"(r0));
    hi = h;
}
__device__ __forceinline__ void split2h(float x0, float x1, uint32_t& hi, uint32_t& lo) {
    x0 *= 256.f; x1 *= 256.f;
    __half2 h = __floats2half2_rn(x0, x1);
    float f0 = __half2float(__low2half(h));
    float f1 = __half2float(__high2half(h));
    __half2 l = __floats2half2_rn(x0 - f0, x1 - f1);
    hi = *(uint32_t*)&h;
    lo = *(uint32_t*)&l;
}
__device__ __forceinline__ void mma16(float* d, const uint32_t* a, const uint32_t* b) {
    asm volatile("mma.sync.aligned.m16n8k16.row.col.f32.bf16.bf16.f32 "
                 "{%0,%1,%2,%3}, {%4,%5,%6,%7}, {%8,%9}, {%0,%1,%2,%3};"
                 : "+f"(d[0]), "+f"(d[1]), "+f"(d[2]), "+f"(d[3])
                 : "r"(a[0]), "r"(a[1]), "r"(a[2]), "r"(a[3]),
                   "r"(b[0]), "r"(b[1]));
}
__device__ __forceinline__ void mma16h(float* d, const uint32_t* a, const uint32_t* b) {
    asm volatile("mma.sync.aligned.m16n8k16.row.col.f32.f16.f16.f32 "
                 "{%0,%1,%2,%3}, {%4,%5,%6,%7}, {%8,%9}, {%0,%1,%2,%3};"
                 : "+f"(d[0]), "+f"(d[1]), "+f"(d[2]), "+f"(d[3])
                 : "r"(a[0]), "r"(a[1]), "r"(a[2]), "r"(a[3]),
                   "r"(b[0]), "r"(b[1]));
}
__device__ __forceinline__ void ldsm4(uint32_t* r, uint32_t a) {
    asm volatile("ldmatrix.sync.aligned.m8n8.x4.shared.b16 {%0,%1,%2,%3}, [%4];"
                 : "=r"(r[0]), "=r"(r[1]), "=r"(r[2]), "=r"(r[3]) : "r"(a));
}
__device__ __forceinline__ float fex2(float z) {
    float r;
    asm("ex2.approx.f32 %0, %1;" : "=f"(r) : "f"(z));
    return r;
}

#define ACC_INIT() float acc[4][4][4];                                           \
    _Pragma("unroll") for (int a_ = 0; a_ < 4; a_++)                             \
    _Pragma("unroll") for (int b_ = 0; b_ < 4; b_++)                             \
    _Pragma("unroll") for (int c_ = 0; c_ < 4; c_++) acc[a_][b_][c_] = 0.f;

// ============================================================================
// prep: split activations + weights into packed-pair arrays
// ============================================================================
__global__ void prep_act(const float* __restrict__ qd, const float* __restrict__ kd,
                         const float* __restrict__ vd)
{
    int idx = blockIdx.x * 256 + threadIdx.x;        // over 3*M_ALL*128
    int which = idx / (M_ALL * 128);
    int r = idx - which * (M_ALL * 128);
    int m = r >> 7, f = r & 127;
    uint32_t h0, l0, h1, l1;
    if (which == 0) {
        float4 v = *(const float4*)(qd + (size_t)m * 512 + f * 4);
        split2h(v.x, v.y, h0, l0); split2h(v.z, v.w, h1, l1);
        *(uint2*)(g_qdh + (size_t)m * 512 + 2 * f)       = make_uint2(h0, h1);
        *(uint2*)(g_qdh + (size_t)m * 512 + 256 + 2 * f) = make_uint2(l0, l1);
        split2(v.x, v.y, h0, l0); split2(v.z, v.w, h1, l1);
        *(uint2*)(g_qd + (size_t)m * 512 + 2 * f)       = make_uint2(h0, h1);
        *(uint2*)(g_qd + (size_t)m * 512 + 256 + 2 * f) = make_uint2(l0, l1);
    } else if (which == 1) {
        float4 v = *(const float4*)(kd + (size_t)m * 512 + f * 4);
        split2h(v.x, v.y, h0, l0); split2h(v.z, v.w, h1, l1);
        *(uint2*)(g_kdh + (size_t)m * 512 + 2 * f)       = make_uint2(h0, h1);
        *(uint2*)(g_kdh + (size_t)m * 512 + 256 + 2 * f) = make_uint2(l0, l1);
    } else {
        float4 v = *(const float4*)(vd + (size_t)m * 512 + f * 4);
        split2(v.x, v.y, h0, l0); split2(v.z, v.w, h1, l1);
        *(uint2*)(g_vdb + (size_t)m * 512 + 2 * f)       = make_uint2(h0, h1);
        *(uint2*)(g_vdb + (size_t)m * 512 + 256 + 2 * f) = make_uint2(l0, l1);
    }
}

__global__ void prep_w(const float* __restrict__ wq, const float* __restrict__ wk,
                       const float* __restrict__ wv, const float* __restrict__ pw,
                       const float* __restrict__ lw)
{
    int idx = blockIdx.x * 256 + threadIdx.x;
    if (idx < 3 * 8 * 256 * 64) {                    // qkv weights, transposed split
        int e = idx & 63;
        int p = (idx >> 6) & 255;
        int h = (idx >> 14) & 7;
        int z = idx >> 17;
        const float* W = ((z == 0) ? wq : (z == 1) ? wk : wv) + (size_t)h * 512 * 64;
        float x0 = W[(size_t)(2 * p) * 64 + e];
        float x1 = W[(size_t)(2 * p + 1) * 64 + e];
        int n = h * 64 + e;
        uint32_t hi, lo;
        if (z == 2) {
            split2(x0, x1, hi, lo);
            g_wvt[(size_t)n * 512 + p] = hi; g_wvt[(size_t)n * 512 + 256 + p] = lo;
        } else {
            split2h(x0, x1, hi, lo);
            uint32_t* dst = (z == 0) ? g_wqt : g_wkt;
            dst[(size_t)n * 512 + p] = hi; dst[(size_t)n * 512 + 256 + p] = lo;
        }
        return;
    }
    idx -= 3 * 8 * 256 * 64;
    uint32_t h0, l0, h1, l1;
    if (idx < 512 * 128) {                           // proj_w
        int n = idx >> 7, f = idx & 127;
        float4 v = *(const float4*)(pw + (size_t)n * 512 + f * 4);
        split2(v.x, v.y, h0, l0); split2(v.z, v.w, h1, l1);
        *(uint2*)(g_pw + (size_t)n * 512 + 2 * f)       = make_uint2(h0, h1);
        *(uint2*)(g_pw + (size_t)n * 512 + 256 + 2 * f) = make_uint2(l0, l1);
        return;
    }
    idx -= 512 * 128;
    if (idx < 512 * 256) {                           // lin_w
        int n = idx >> 8, f = idx & 255;
        float4 v = *(const float4*)(lw + (size_t)n * 1024 + f * 4);
        split2(v.x, v.y, h0, l0); split2(v.z, v.w, h1, l1);
        *(uint2*)(g_lw + (size_t)n * 1024 + 2 * f)       = make_uint2(h0, h1);
        *(uint2*)(g_lw + (size_t)n * 1024 + 512 + 2 * f) = make_uint2(l0, l1);
    }
}

// ============================================================================
// Unified pre-split GEMM core: pure ldmatrix+HMMA. 128x64 CTA tile, 4 warps
// 2(M)x2(N), warp tile 64x32, chunks of 16 pairs (k=32). 2-stage cp.async
// pipeline with ONE barrier per chunk (wait0 -> sync -> prefetch c+1 ->
// compute c); 3 CTAs/SM.
// EPI: 0 = packed fp16 x256, 1 = fp32, 2 = packed bf16 + bias, 3 = fp32 + bias
// ============================================================================
#define PKPAD 36
#define PK_SMEM ((2*128*PKPAD + 2*64*PKPAD)*4)   /* 55296 */

template<bool FP16, int EPI>
__device__ __forceinline__ void pk_core(
    const uint32_t* __restrict__ A1, const uint32_t* __restrict__ A2, int K1p, int Kp,
    const uint32_t* __restrict__ Bm, int ldb,
    const float* __restrict__ bias, float* __restrict__ Cf, uint32_t* __restrict__ Cp,
    int m0, int n0, uint32_t* smu)
{
    uint32_t* Abuf[2] = { smu,               smu + 128*PKPAD };
    uint32_t* Bbuf[2] = { smu + 2*128*PKPAD, smu + 2*128*PKPAD + 64*PKPAD };
    const int tid = threadIdx.x;
    const int wid = tid >> 5, lane = tid & 31;
    const int wm = wid & 1, wn = wid >> 1;
    const int lr = lane >> 2, lc = lane & 3;
    const int NC = Kp / 16;
    const int lob = ldb >> 1;

    const int a_off = ((lane&7) + ((lane>>3)&1)*8)*PKPAD + (lane>>4)*4;
    const int b_off = (lane&7)*PKPAD + ((lane>>3)&1)*4 + (lane>>4)*16;
    uint32_t a_sh[2], b_sh[2];
    a_sh[0] = smem_u32(Abuf[0]) + (wm*64*PKPAD + a_off)*4;
    a_sh[1] = smem_u32(Abuf[1]) + (wm*64*PKPAD + a_off)*4;
    b_sh[0] = smem_u32(Bbuf[0]) + (wn*32*PKPAD + b_off)*4;
    b_sh[1] = smem_u32(Bbuf[1]) + (wn*32*PKPAD + b_off)*4;

#define A_LOADP(buf, c_) do {                                                     \
        int p0_; const uint32_t* Asrc;                                            \
        if ((c_)*16 < K1p) { Asrc = A1; p0_ = (c_)*16; }                          \
        else               { Asrc = A2; p0_ = (c_)*16 - K1p; }                    \
        _Pragma("unroll")                                                         \
        for (int i = 0; i < 4; i++) {                                             \
            int id = tid + i * 128;                                               \
            int row = id >> 2, seg = (id & 3) * 4;                                \
            cp_async16(Abuf[buf] + row*PKPAD + seg,                               \
                       Asrc + (size_t)(m0 + row)*512 + p0_ + seg);                \
        }                                                                          \
        _Pragma("unroll")                                                         \
        for (int i = 0; i < 4; i++) {                                             \
            int id = tid + i * 128;                                               \
            int row = id >> 2, seg = (id & 3) * 4;                                \
            cp_async16(Abuf[buf] + row*PKPAD + 16 + seg,                          \
                       Asrc + (size_t)(m0 + row)*512 + 256 + p0_ + seg);          \
        }                                                                          \
    } while (0)
#define B_LOADP(buf, c_) do {                                                     \
        int p0_ = (c_) * 16;                                                      \
        _Pragma("unroll")                                                         \
        for (int i = 0; i < 2; i++) {                                             \
            int id = tid + i * 128;                                               \
            int row = id >> 2, seg = (id & 3) * 4;                                \
            cp_async16(Bbuf[buf] + row*PKPAD + seg,                               \
                       Bm + (size_t)(n0 + row)*ldb + p0_ + seg);                  \
        }                                                                          \
        _Pragma("unroll")                                                         \
        for (int i = 0; i < 2; i++) {                                             \
            int id = tid + i * 128;                                               \
            int row = id >> 2, seg = (id & 3) * 4;                                \
            cp_async16(Bbuf[buf] + row*PKPAD + 16 + seg,                          \
                       Bm + (size_t)(n0 + row)*ldb + lob + p0_ + seg);            \
        }                                                                          \
    } while (0)

    A_LOADP(0, 0); B_LOADP(0, 0); CP_COMMIT();
    ACC_INIT()

    int buf = 0;
    for (int c = 0; c < NC; c++) {
        CP_WAIT0();                 // this thread's copies for chunk c complete
        __syncthreads();            // publish chunk c; all warps done reading buf^1
        if (c + 1 < NC) {           // prefetch c+1 into the buffer just freed
            A_LOADP(buf ^ 1, c + 1); B_LOADP(buf ^ 1, c + 1); CP_COMMIT();
        }
#pragma unroll
        for (int ks = 0; ks < 2; ks++) {
            uint32_t bfr[4][4];
#pragma unroll
            for (int nt = 0; nt < 4; nt++)
                ldsm4(bfr[nt], b_sh[buf] + (nt*8*PKPAD + ks*8)*4);
#pragma unroll
            for (int mt = 0; mt < 4; mt++) {
                uint32_t ah[4], al[4];
                uint32_t aa = a_sh[buf] + (mt*16*PKPAD + ks*8)*4;
                ldsm4(ah, aa);
                ldsm4(al, aa + 64);
#pragma unroll
                for (int nt = 0; nt < 4; nt++) {
                    if (FP16) {
                        mma16h(acc[mt][nt], ah, bfr[nt]);
                        mma16h(acc[mt][nt], ah, bfr[nt] + 2);
                        mma16h(acc[mt][nt], al, bfr[nt]);
                    } else {
                        mma16(acc[mt][nt], ah, bfr[nt]);
                        mma16(acc[mt][nt], ah, bfr[nt] + 2);
                        mma16(acc[mt][nt], al, bfr[nt]);
                    }
                }
            }
        }
        buf ^= 1;
    }

#pragma unroll
    for (int mt = 0; mt < 4; mt++) {
#pragma unroll
        for (int nt = 0; nt < 4; nt++) {
            int row = m0 + wm*64 + mt*16 + lr;
            if (EPI == 0) {
                int colp = wn*16 + nt*4 + lc;
                uint32_t hi, lo;
                split2h(acc[mt][nt][0]*UNSC, acc[mt][nt][1]*UNSC, hi, lo);
                Cp[(size_t)row*512 + n0 + colp]      = hi;
                Cp[(size_t)row*512 + n0 + 32 + colp] = lo;
                split2h(acc[mt][nt][2]*UNSC, acc[mt][nt][3]*UNSC, hi, lo);
                Cp[(size_t)(row+8)*512 + n0 + colp]      = hi;
                Cp[(size_t)(row+8)*512 + n0 + 32 + colp] = lo;
            } else if (EPI == 1) {
                int col = n0 + wn*32 + nt*8 + 2*lc;
                *(float2*)(Cf + (size_t)row * Dm + col) =
                    make_float2(acc[mt][nt][0], acc[mt][nt][1]);
                *(float2*)(Cf + (size_t)(row + 8) * Dm + col) =
                    make_float2(acc[mt][nt][2], acc[mt][nt][3]);
            } else if (EPI == 2) {
                int col = n0 + wn*32 + nt*8 + 2*lc;
                float bx = bias[col], by = bias[col + 1];
                int pair = col >> 1;
                uint32_t hi, lo;
                split2(acc[mt][nt][0] + bx, acc[mt][nt][1] + by, hi, lo);
                Cp[(size_t)row*512 + pair] = hi;
                Cp[(size_t)row*512 + 256 + pair] = lo;
                split2(acc[mt][nt][2] + bx, acc[mt][nt][3] + by, hi, lo);
                Cp[(size_t)(row+8)*512 + pair] = hi;
                Cp[(size_t)(row+8)*512 + 256 + pair] = lo;
            } else {
                int col = n0 + wn*32 + nt*8 + 2*lc;
                float bx = bias[col], by = bias[col + 1];
                *(float2*)(Cf + (size_t)row * Dm + col) =
                    make_float2(acc[mt][nt][0] + bx, acc[mt][nt][1] + by);
                *(float2*)(Cf + (size_t)(row + 8) * Dm + col) =
                    make_float2(acc[mt][nt][2] + bx, acc[mt][nt][3] + by);
            }
        }
    }
#undef A_LOADP
#undef B_LOADP
}

__global__ __launch_bounds__(128, 3) void qkv_pk()
{
    extern __shared__ uint32_t smu[];
    const int z = blockIdx.z;
    const int m0 = blockIdx.y * 128, n0 = blockIdx.x * 64;
    if (z == 0)
        pk_core<true, 0>(g_qdh, g_qdh, 256, 256, g_wqt, 512, nullptr, nullptr, g_q, m0, n0, smu);
    else if (z == 1)
        pk_core<true, 0>(g_kdh, g_kdh, 256, 256, g_wkt, 512, nullptr, nullptr, g_k, m0, n0, smu);
    else
        pk_core<false, 1>(g_vdb, g_vdb, 256, 256, g_wvt, 512, nullptr, g_vs, nullptr, m0, n0, smu);
}

__global__ __launch_bounds__(128, 3) void proj_pk(const float* __restrict__ bias)
{
    extern __shared__ uint32_t smu[];
    pk_core<false, 2>(g_ho, g_ho, 256, 256, g_pw, 512, bias, nullptr, g_po,
                      blockIdx.y * 128, blockIdx.x * 64, smu);
}

__global__ __launch_bounds__(128, 3) void lin_pk(const float* __restrict__ bias,
                                                 float* __restrict__ out)
{
    extern __shared__ uint32_t smu[];
    pk_core<false, 3>(g_qd, g_po, 256, 512, g_lw, 1024, bias, out, nullptr,
                      blockIdx.y * 128, blockIdx.x * 64, smu);
}

// ============================================================================
// QK^T (ldmatrix + fp16 HMMA) + softmax stats + dense attn fill, fused.
// CTA = (h, b, 128 q rows); 16 K-tiles of 64 rows. (R11 verbatim)
// ============================================================================
#define APADU 68
#define S_SMEM ((128*APADU + 2*64*APADU)*4 + 256*4*3)  /* 72704 */
__global__ __launch_bounds__(128, 3) void attn_stats_mma(float* __restrict__ attn)
{
    extern __shared__ uint32_t smu[];
    uint32_t* Qs = smu;
    uint32_t* Kbuf[2] = { smu + 128*APADU, smu + 128*APADU + 64*APADU };
    float* redm = (float*)(smu + 128*APADU + 2*64*APADU);
    float* reds = redm + 256;
    int*   redi = (int*)(reds + 256);

    const int tid = threadIdx.x;
    const int h = blockIdx.z, b = blockIdx.y, q0 = blockIdx.x * 128;
    const int wid = tid >> 5, lane = tid & 31;
    const int wm = wid & 1, wn = wid >> 1;
    const int lr = lane >> 2, lc = lane & 3;

    const uint32_t* Qg = g_q + ((size_t)(b * Ls + q0)) * 512 + h * 64;
    const uint32_t* Kg = g_k + ((size_t)(b * Ls)) * 512 + h * 64;
    const size_t rowbase = (size_t)(h * Bn + b) * Ls + q0;

    const int a_off = ((lane&7) + ((lane>>3)&1)*8)*APADU + (lane>>4)*4;
    const int b_off = (lane&7)*APADU + ((lane>>3)&1)*4 + (lane>>4)*32;
    const uint32_t qs_sh = smem_u32(Qs) + (wm*64*APADU + a_off)*4;
    uint32_t k_sh[2];
    k_sh[0] = smem_u32(Kbuf[0]) + (wn*32*APADU + b_off)*4;
    k_sh[1] = smem_u32(Kbuf[1]) + (wn*32*APADU + b_off)*4;

#pragma unroll
    for (int i = 0; i < 16; i++) {
        int id = tid + i * 128;
        int row = id >> 4, seg = (id & 15) * 4;
        cp_async16(Qs + row*APADU + seg, Qg + (size_t)row * 512 + seg);
    }
    CP_COMMIT();

#define K_LOAD(buf, t_) do {                                                    \
        _Pragma("unroll")                                                       \
        for (int i = 0; i < 8; i++) {                                           \
            int id = tid + i * 128;                                             \
            int row = id >> 4, seg = (id & 15) * 4;                             \
            cp_async16(Kbuf[buf] + row*APADU + seg,                             \
                       Kg + (size_t)((t_)*64 + row) * 512 + seg);               \
        }                                                                       \
    } while (0)

    K_LOAD(0, 0); CP_COMMIT();
    K_LOAD(1, 1); CP_COMMIT();

    float rm[8], rs[8];
    int ridx[8];
#pragma unroll
    for (int i = 0; i < 8; i++) { rm[i] = -1e30f; rs[i] = 0.f; ridx[i] = 0; }

    for (int t = 0; t < 16; t++) {
        if (t < 15) CP_WAIT1(); else CP_WAIT0();
        __syncthreads();
        const int buf = t & 1;

        ACC_INIT()

#pragma unroll
        for (int ks = 0; ks < 4; ks++) {
            uint32_t bfr[4][4];
#pragma unroll
            for (int nt = 0; nt < 4; nt++)
                ldsm4(bfr[nt], k_sh[buf] + (nt*8*APADU + ks*8)*4);
#pragma unroll
            for (int mt = 0; mt < 4; mt++) {
                uint32_t ah[4], al[4];
                uint32_t aa = qs_sh + (mt*16*APADU + ks*8)*4;
                ldsm4(ah, aa);
                ldsm4(al, aa + 128);
#pragma unroll
                for (int nt = 0; nt < 4; nt++) {
                    mma16h(acc[mt][nt], ah, bfr[nt]);
                    mma16h(acc[mt][nt], ah, bfr[nt] + 2);
                    mma16h(acc[mt][nt], al, bfr[nt]);
                }
            }
        }

        // streaming zero-fill of this CTA's attn slice, s-range [t*64, t*64+64)
        {
            float4 z4 = make_float4(0.f, 0.f, 0.f, 0.f);
#pragma unroll
            for (int i = 0; i < 16; i++) {
                int id = tid + i * 128;
                int r = id >> 4, f4 = id & 15;
                __stcs((float4*)(attn + (rowbase + r) * Ls + t * 64 + f4 * 4), z4);
            }
        }

        // fold tile into per-thread stats (per-score predicated; R11 form)
        const int sbase = t * 64 + wn * 32 + 2 * lc;
#pragma unroll
        for (int mt = 0; mt < 4; mt++) {
#pragma unroll
            for (int half = 0; half < 2; half++) {
                const int r8 = mt * 2 + half;
                float m = rm[r8], s_ = rs[r8];
                int id_ = ridx[r8];
#pragma unroll
                for (int nt = 0; nt < 4; nt++) {
#pragma unroll
                    for (int j = 0; j < 2; j++) {
                        float v = acc[mt][nt][half*2 + j];
                        if (v > m) { m = v; id_ = sbase + nt*8 + j; }
                        s_ += fex2(v * CCH);
                    }
                }
                rm[r8] = m; rs[r8] = s_; ridx[r8] = id_;
            }
        }
        __syncthreads();
        if (t + 2 < 16) { K_LOAD(buf, t + 2); CP_COMMIT(); }
    }

    // quad reduce over lc
#pragma unroll
    for (int r8 = 0; r8 < 8; r8++) {
        float m = rm[r8], s_ = rs[r8];
        int id_ = ridx[r8];
#pragma unroll
        for (int off = 1; off <= 2; off <<= 1) {
            float om = __shfl_xor_sync(0xffffffffu, m, off);
            float os = __shfl_xor_sync(0xffffffffu, s_, off);
            int   oi = __shfl_xor_sync(0xffffffffu, id_, off);
            s_ += os;
            if (om > m) { m = om; id_ = oi; }
        }
        if (lc == 0) {
            int rowl = wm*64 + (r8 >> 1)*16 + (r8 & 1)*8 + lr;
            redm[rowl*2 + wn] = m;
            reds[rowl*2 + wn] = s_;
            redi[rowl*2 + wn] = id_;
        }
    }
    __syncthreads();

    {
        float m = redm[tid*2], s_ = reds[tid*2];
        int id_ = redi[tid*2];
        float om = redm[tid*2 + 1];
        s_ += reds[tid*2 + 1];
        if (om > m) { m = om; id_ = redi[tid*2 + 1]; }
        float p = fex2(m * CCH) / s_;
        int row = (int)(rowbase) + tid;
        g_p[row] = p;
        g_amax[row] = id_;
        attn[(rowbase + tid) * Ls + id_] = p;
    }
#undef K_LOAD
}

// ============================================================================
// attn @ V gather -> packed bf16 headout pairs (standalone, coalesced)
// ============================================================================
__global__ void gather_kernel()
{
    int idx4 = blockIdx.x * blockDim.x + threadIdx.x;
    if (idx4 >= M_ALL * Dm / 4) return;
    int e4 = idx4 & 15;
    int h  = (idx4 >> 4) & 7;
    int m  = idx4 >> 7;
    int b  = m >> 10;
    int q  = m & 1023;
    int row = (h * Bn + b) * Ls + q;
    float p = g_p[row];
    int   s = g_amax[row];
    float4 v = *(const float4*)(g_vs + ((size_t)(b * Ls + s)) * Dm + h * 64 + e4 * 4);
    uint32_t h0, l0, h1, l1;
    split2(v.x * p, v.y * p, h0, l0);
    split2(v.z * p, v.w * p, h1, l1);
    int pairbase = h * 32 + e4 * 2;
    *(uint2*)(g_ho + (size_t)m * 512 + pairbase)       = make_uint2(h0, h1);
    *(uint2*)(g_ho + (size_t)m * 512 + 256 + pairbase) = make_uint2(l0, l1);
}

// ============================================================================
extern "C" void kernel_launch(void* const* d_in, const int* in_sizes, int n_in,
                              void* d_out, int out_size)
{
    const float* q_data = (const float*)d_in[0];
    const float* k_data = (const float*)d_in[1];
    const float* v_data = (const float*)d_in[2];
    const float* w_qs   = (const float*)d_in[3];
    const float* w_ks   = (const float*)d_in[4];
    const float* w_vs   = (const float*)d_in[5];
    const float* proj_w = (const float*)d_in[6];
    const float* proj_b = (const float*)d_in[7];
    const float* lin_w  = (const float*)d_in[8];
    const float* lin_b  = (const float*)d_in[9];

    float* out  = (float*)d_out;                    // [B, L, D]
    float* attn = out + OUT_ELEMS;                  // [H*B, L, L]

    cudaFuncSetAttribute(qkv_pk,  cudaFuncAttributeMaxDynamicSharedMemorySize, PK_SMEM);
    cudaFuncSetAttribute(proj_pk, cudaFuncAttributeMaxDynamicSharedMemorySize, PK_SMEM);
    cudaFuncSetAttribute(lin_pk,  cudaFuncAttributeMaxDynamicSharedMemorySize, PK_SMEM);
    cudaFuncSetAttribute(attn_stats_mma, cudaFuncAttributeMaxDynamicSharedMemorySize, S_SMEM);

    // 0) pre-split all MMA inputs into packed-pair arrays
    prep_act<<<3 * M_ALL * 128 / 256, 256>>>(q_data, k_data, v_data);
    prep_w<<<(3*8*256*64 + 512*128 + 512*256 + 255) / 256, 256>>>(w_qs, w_ks, w_vs,
                                                                  proj_w, lin_w);

    // 1) Q/K/V projections (single-barrier 2-stage pipeline, 3 CTAs/SM)
    qkv_pk<<<dim3(8, 128, 3), 128, PK_SMEM>>>();

    // 2) QK^T + softmax stats + dense attn fill
    attn_stats_mma<<<dim3(8, 16, 8), 128, S_SMEM>>>(attn);

    // 3) attn @ V gather -> packed bf16 headout
    gather_kernel<<<(M_ALL * Dm / 4 + 255) / 256, 256>>>();

    // 4) output projection -> packed bf16 projout
    proj_pk<<<dim3(8, 128), 128, PK_SMEM>>>(proj_b);

    // 5) final linear: out = [q_data | projout] @ lin_w^T + lin_b
    lin_pk<<<dim3(8, 128), 128, PK_SMEM>>>(lin_b, out);
}

// round 17
// speedup vs baseline: 1.1058x; 1.0422x over previous
#include <cuda_runtime.h>
#include <cuda_fp16.h>
#include <cstdint>

#define Hh 8
#define Bn 16
#define Ls 1024
#define Dm 512
#define M_ALL (Bn*Ls)              /* 16384 */
#define OUT_ELEMS (Bn*Ls*Dm)       /* 8388608 */
#define NROWS (Hh*Bn*Ls)           /* 131072 */
#define CCH  9.728829e-7f          /* (1/sqrt(512))*log2(e)/65536 */
#define UNSC 1.52587890625e-5f     /* 2^-16 */

// ---------------- static device scratch (packed-pair u32 = 2 b16, consec k) --
__device__ uint32_t g_q  [M_ALL*512];   // Q proj, fp16 x256; head h: hi [h*64..+32), lo [+32..+64)
__device__ uint32_t g_k  [M_ALL*512];
__device__ float    g_vs [M_ALL*Dm];    // V proj fp32
__device__ uint32_t g_ho [M_ALL*512];   // headout bf16: hi [0,256), lo [256,512)
__device__ uint32_t g_po [M_ALL*512];   // projout bf16
__device__ uint32_t g_qd [M_ALL*512];   // q_data bf16 (lin A1)
__device__ uint32_t g_qdh[M_ALL*512];   // q_data fp16 x256 (Q proj A)
__device__ uint32_t g_kdh[M_ALL*512];   // k_data fp16 x256
__device__ uint32_t g_vdb[M_ALL*512];   // v_data bf16
__device__ uint32_t g_wqt[512*512];     // wq^T fp16 x256: [n=h*64+e][hi 256 | lo 256]
__device__ uint32_t g_wkt[512*512];
__device__ uint32_t g_wvt[512*512];     // bf16
__device__ uint32_t g_pw [512*512];     // proj_w bf16 [n][hi 256|lo 256]
__device__ uint32_t g_lw [512*1024];    // lin_w bf16 [n][hi 512|lo 512]
__device__ float g_p[NROWS];
__device__ int   g_amax[NROWS];

// ---------------- helpers ----------------
__device__ __forceinline__ uint32_t smem_u32(const void* p) {
    uint32_t a;
    asm("{ .reg .u64 t; cvta.to.shared.u64 t, %1; cvt.u32.u64 %0, t; }" : "=r"(a) : "l"(p));
    return a;
}
__device__ __forceinline__ void cp_async16(void* sdst, const void* gsrc) {
    uint32_t s = smem_u32(sdst);
    asm volatile("cp.async.ca.shared.global [%0], [%1], 16;" :: "r"(s), "l"(gsrc));
}
#define CP_COMMIT() asm volatile("cp.async.commit_group;" ::: "memory")
#define CP_WAIT0()  asm volatile("cp.async.wait_group 0;" ::: "memory")

__device__ __forceinline__ void split2(float x0, float x1, uint32_t& hi, uint32_t& lo) {
    uint32_t h;
    asm("cvt.rn.bf16x2.f32 %0, %1, %2;" : "=r"(h) : "f"(x1), "f"(x0));
    float h0 = __uint_as_float(h << 16);
    float h1 = __uint_as_float(h & 0xffff0000u);
    float r0 = x0 - h0, r1 = x1 - h1;
    asm("cvt.rn.bf16x2.f32 %0, %1, %2;" : "=r"(lo) : "f"(r1), "f"(r0));
    hi = h;
}
__device__ __forceinline__ void split2h(float x0, float x1, uint32_t& hi, uint32_t& lo) {
    x0 *= 256.f; x1 *= 256.f;
    __half2 h = __floats2half2_rn(x0, x1);
    float f0 = __half2float(__low2half(h));
    float f1 = __half2float(__high2half(h));
    __half2 l = __floats2half2_rn(x0 - f0, x1 - f1);
    hi = *(uint32_t*)&h;
    lo = *(uint32_t*)&l;
}
__device__ __forceinline__ void mma16(float* d, const uint32_t* a, const uint32_t* b) {
    asm volatile("mma.sync.aligned.m16n8k16.row.col.f32.bf16.bf16.f32 "
                 "{%0,%1,%2,%3}, {%4,%5,%6,%7}, {%8,%9}, {%0,%1,%2,%3};"
                 : "+f"(d[0]), "+f"(d[1]), "+f"(d[2]), "+f"(d[3])
                 : "r"(a[0]), "r"(a[1]), "r"(a[2]), "r"(a[3]),
                   "r"(b[0]), "r"(b[1]));
}
__device__ __forceinline__ void mma16h(float* d, const uint32_t* a, const uint32_t* b) {
    asm volatile("mma.sync.aligned.m16n8k16.row.col.f32.f16.f16.f32 "
                 "{%0,%1,%2,%3}, {%4,%5,%6,%7}, {%8,%9}, {%0,%1,%2,%3};"
                 : "+f"(d[0]), "+f"(d[1]), "+f"(d[2]), "+f"(d[3])
                 : "r"(a[0]), "r"(a[1]), "r"(a[2]), "r"(a[3]),
                   "r"(b[0]), "r"(b[1]));
}
__device__ __forceinline__ void ldsm4(uint32_t* r, uint32_t a) {
    asm volatile("ldmatrix.sync.aligned.m8n8.x4.shared.b16 {%0,%1,%2,%3}, [%4];"
                 : "=r"(r[0]), "=r"(r[1]), "=r"(r[2]), "=r"(r[3]) : "r"(a));
}
__device__ __forceinline__ float fex2(float z) {
    float r;
    asm("ex2.approx.f32 %0, %1;" : "=f"(r) : "f"(z));
    return r;
}

#define ACC_INIT() float acc[4][4][4];                                           \
    _Pragma("unroll") for (int a_ = 0; a_ < 4; a_++)                             \
    _Pragma("unroll") for (int b_ = 0; b_ < 4; b_++)                             \
    _Pragma("unroll") for (int c_ = 0; c_ < 4; c_++) acc[a_][b_][c_] = 0.f;

// ============================================================================
// prep: split activations + weights into packed-pair arrays
// ============================================================================
__global__ void prep_act(const float* __restrict__ qd, const float* __restrict__ kd,
                         const float* __restrict__ vd)
{
    int idx = blockIdx.x * 256 + threadIdx.x;        // over 3*M_ALL*128
    int which = idx / (M_ALL * 128);
    int r = idx - which * (M_ALL * 128);
    int m = r >> 7, f = r & 127;
    uint32_t h0, l0, h1, l1;
    if (which == 0) {
        float4 v = *(const float4*)(qd + (size_t)m * 512 + f * 4);
        split2h(v.x, v.y, h0, l0); split2h(v.z, v.w, h1, l1);
        *(uint2*)(g_qdh + (size_t)m * 512 + 2 * f)       = make_uint2(h0, h1);
        *(uint2*)(g_qdh + (size_t)m * 512 + 256 + 2 * f) = make_uint2(l0, l1);
        split2(v.x, v.y, h0, l0); split2(v.z, v.w, h1, l1);
        *(uint2*)(g_qd + (size_t)m * 512 + 2 * f)       = make_uint2(h0, h1);
        *(uint2*)(g_qd + (size_t)m * 512 + 256 + 2 * f) = make_uint2(l0, l1);
    } else if (which == 1) {
        float4 v = *(const float4*)(kd + (size_t)m * 512 + f * 4);
        split2h(v.x, v.y, h0, l0); split2h(v.z, v.w, h1, l1);
        *(uint2*)(g_kdh + (size_t)m * 512 + 2 * f)       = make_uint2(h0, h1);
        *(uint2*)(g_kdh + (size_t)m * 512 + 256 + 2 * f) = make_uint2(l0, l1);
    } else {
        float4 v = *(const float4*)(vd + (size_t)m * 512 + f * 4);
        split2(v.x, v.y, h0, l0); split2(v.z, v.w, h1, l1);
        *(uint2*)(g_vdb + (size_t)m * 512 + 2 * f)       = make_uint2(h0, h1);
        *(uint2*)(g_vdb + (size_t)m * 512 + 256 + 2 * f) = make_uint2(l0, l1);
    }
}

__global__ void prep_w(const float* __restrict__ wq, const float* __restrict__ wk,
                       const float* __restrict__ wv, const float* __restrict__ pw,
                       const float* __restrict__ lw)
{
    int idx = blockIdx.x * 256 + threadIdx.x;
    if (idx < 3 * 8 * 256 * 64) {                    // qkv weights, transposed split
        int e = idx & 63;
        int p = (idx >> 6) & 255;
        int h = (idx >> 14) & 7;
        int z = idx >> 17;
        const float* W = ((z == 0) ? wq : (z == 1) ? wk : wv) + (size_t)h * 512 * 64;
        float x0 = W[(size_t)(2 * p) * 64 + e];
        float x1 = W[(size_t)(2 * p + 1) * 64 + e];
        int n = h * 64 + e;
        uint32_t hi, lo;
        if (z == 2) {
            split2(x0, x1, hi, lo);
            g_wvt[(size_t)n * 512 + p] = hi; g_wvt[(size_t)n * 512 + 256 + p] = lo;
        } else {
            split2h(x0, x1, hi, lo);
            uint32_t* dst = (z == 0) ? g_wqt : g_wkt;
            dst[(size_t)n * 512 + p] = hi; dst[(size_t)n * 512 + 256 + p] = lo;
        }
        return;
    }
    idx -= 3 * 8 * 256 * 64;
    uint32_t h0, l0, h1, l1;
    if (idx < 512 * 128) {                           // proj_w
        int n = idx >> 7, f = idx & 127;
        float4 v = *(const float4*)(pw + (size_t)n * 512 + f * 4);
        split2(v.x, v.y, h0, l0); split2(v.z, v.w, h1, l1);
        *(uint2*)(g_pw + (size_t)n * 512 + 2 * f)       = make_uint2(h0, h1);
        *(uint2*)(g_pw + (size_t)n * 512 + 256 + 2 * f) = make_uint2(l0, l1);
        return;
    }
    idx -= 512 * 128;
    if (idx < 512 * 256) {                           // lin_w
        int n = idx >> 8, f = idx & 255;
        float4 v = *(const float4*)(lw + (size_t)n * 1024 + f * 4);
        split2(v.x, v.y, h0, l0); split2(v.z, v.w, h1, l1);
        *(uint2*)(g_lw + (size_t)n * 1024 + 2 * f)       = make_uint2(h0, h1);
        *(uint2*)(g_lw + (size_t)n * 1024 + 512 + 2 * f) = make_uint2(l0, l1);
    }
}

// ============================================================================
// Unified pre-split GEMM core: pure ldmatrix+HMMA. 128x64 CTA tile, 4 warps
// 2(M)x2(N), warp tile 64x32, chunks of 16 pairs (k=32). 2-stage cp.async
// pipeline with ONE barrier per chunk; 3 CTAs/SM. (R16, proven)
// EPI: 0 = packed fp16 x256, 1 = fp32, 2 = packed bf16 + bias, 3 = fp32 + bias
// ============================================================================
#define PKPAD 36
#define PK_SMEM ((2*128*PKPAD + 2*64*PKPAD)*4)   /* 55296 */

template<bool FP16, int EPI>
__device__ __forceinline__ void pk_core(
    const uint32_t* __restrict__ A1, const uint32_t* __restrict__ A2, int K1p, int Kp,
    const uint32_t* __restrict__ Bm, int ldb,
    const float* __restrict__ bias, float* __restrict__ Cf, uint32_t* __restrict__ Cp,
    int m0, int n0, uint32_t* smu)
{
    uint32_t* Abuf[2] = { smu,               smu + 128*PKPAD };
    uint32_t* Bbuf[2] = { smu + 2*128*PKPAD, smu + 2*128*PKPAD + 64*PKPAD };
    const int tid = threadIdx.x;
    const int wid = tid >> 5, lane = tid & 31;
    const int wm = wid & 1, wn = wid >> 1;
    const int lr = lane >> 2, lc = lane & 3;
    const int NC = Kp / 16;
    const int lob = ldb >> 1;

    const int a_off = ((lane&7) + ((lane>>3)&1)*8)*PKPAD + (lane>>4)*4;
    const int b_off = (lane&7)*PKPAD + ((lane>>3)&1)*4 + (lane>>4)*16;
    uint32_t a_sh[2], b_sh[2];
    a_sh[0] = smem_u32(Abuf[0]) + (wm*64*PKPAD + a_off)*4;
    a_sh[1] = smem_u32(Abuf[1]) + (wm*64*PKPAD + a_off)*4;
    b_sh[0] = smem_u32(Bbuf[0]) + (wn*32*PKPAD + b_off)*4;
    b_sh[1] = smem_u32(Bbuf[1]) + (wn*32*PKPAD + b_off)*4;

#define A_LOADP(buf, c_) do {                                                     \
        int p0_; const uint32_t* Asrc;                                            \
        if ((c_)*16 < K1p) { Asrc = A1; p0_ = (c_)*16; }                          \
        else               { Asrc = A2; p0_ = (c_)*16 - K1p; }                    \
        _Pragma("unroll")                                                         \
        for (int i = 0; i < 4; i++) {                                             \
            int id = tid + i * 128;                                               \
            int row = id >> 2, seg = (id & 3) * 4;                                \
            cp_async16(Abuf[buf] + row*PKPAD + seg,                               \
                       Asrc + (size_t)(m0 + row)*512 + p0_ + seg);                \
        }                                                                          \
        _Pragma("unroll")                                                         \
        for (int i = 0; i < 4; i++) {                                             \
            int id = tid + i * 128;                                               \
            int row = id >> 2, seg = (id & 3) * 4;                                \
            cp_async16(Abuf[buf] + row*PKPAD + 16 + seg,                          \
                       Asrc + (size_t)(m0 + row)*512 + 256 + p0_ + seg);          \
        }                                                                          \
    } while (0)
#define B_LOADP(buf, c_) do {                                                     \
        int p0_ = (c_) * 16;                                                      \
        _Pragma("unroll")                                                         \
        for (int i = 0; i < 2; i++) {                                             \
            int id = tid + i * 128;                                               \
            int row = id >> 2, seg = (id & 3) * 4;                                \
            cp_async16(Bbuf[buf] + row*PKPAD + seg,                               \
                       Bm + (size_t)(n0 + row)*ldb + p0_ + seg);                  \
        }                                                                          \
        _Pragma("unroll")                                                         \
        for (int i = 0; i < 2; i++) {                                             \
            int id = tid + i * 128;                                               \
            int row = id >> 2, seg = (id & 3) * 4;                                \
            cp_async16(Bbuf[buf] + row*PKPAD + 16 + seg,                          \
                       Bm + (size_t)(n0 + row)*ldb + lob + p0_ + seg);            \
        }                                                                          \
    } while (0)

    A_LOADP(0, 0); B_LOADP(0, 0); CP_COMMIT();
    ACC_INIT()

    int buf = 0;
    for (int c = 0; c < NC; c++) {
        CP_WAIT0();                 // this thread's copies for chunk c complete
        __syncthreads();            // publish chunk c; all warps done reading buf^1
        if (c + 1 < NC) {           // prefetch c+1 into the buffer just freed
            A_LOADP(buf ^ 1, c + 1); B_LOADP(buf ^ 1, c + 1); CP_COMMIT();
        }
#pragma unroll
        for (int ks = 0; ks < 2; ks++) {
            uint32_t bfr[4][4];
#pragma unroll
            for (int nt = 0; nt < 4; nt++)
                ldsm4(bfr[nt], b_sh[buf] + (nt*8*PKPAD + ks*8)*4);
#pragma unroll
            for (int mt = 0; mt < 4; mt++) {
                uint32_t ah[4], al[4];
                uint32_t aa = a_sh[buf] + (mt*16*PKPAD + ks*8)*4;
                ldsm4(ah, aa);
                ldsm4(al, aa + 64);
#pragma unroll
                for (int nt = 0; nt < 4; nt++) {
                    if (FP16) {
                        mma16h(acc[mt][nt], ah, bfr[nt]);
                        mma16h(acc[mt][nt], ah, bfr[nt] + 2);
                        mma16h(acc[mt][nt], al, bfr[nt]);
                    } else {
                        mma16(acc[mt][nt], ah, bfr[nt]);
                        mma16(acc[mt][nt], ah, bfr[nt] + 2);
                        mma16(acc[mt][nt], al, bfr[nt]);
                    }
                }
            }
        }
        buf ^= 1;
    }

#pragma unroll
    for (int mt = 0; mt < 4; mt++) {
#pragma unroll
        for (int nt = 0; nt < 4; nt++) {
            int row = m0 + wm*64 + mt*16 + lr;
            if (EPI == 0) {
                int colp = wn*16 + nt*4 + lc;
                uint32_t hi, lo;
                split2h(acc[mt][nt][0]*UNSC, acc[mt][nt][1]*UNSC, hi, lo);
                Cp[(size_t)row*512 + n0 + colp]      = hi;
                Cp[(size_t)row*512 + n0 + 32 + colp] = lo;
                split2h(acc[mt][nt][2]*UNSC, acc[mt][nt][3]*UNSC, hi, lo);
                Cp[(size_t)(row+8)*512 + n0 + colp]      = hi;
                Cp[(size_t)(row+8)*512 + n0 + 32 + colp] = lo;
            } else if (EPI == 1) {
                int col = n0 + wn*32 + nt*8 + 2*lc;
                *(float2*)(Cf + (size_t)row * Dm + col) =
                    make_float2(acc[mt][nt][0], acc[mt][nt][1]);
                *(float2*)(Cf + (size_t)(row + 8) * Dm + col) =
                    make_float2(acc[mt][nt][2], acc[mt][nt][3]);
            } else if (EPI == 2) {
                int col = n0 + wn*32 + nt*8 + 2*lc;
                float bx = bias[col], by = bias[col + 1];
                int pair = col >> 1;
                uint32_t hi, lo;
                split2(acc[mt][nt][0] + bx, acc[mt][nt][1] + by, hi, lo);
                Cp[(size_t)row*512 + pair] = hi;
                Cp[(size_t)row*512 + 256 + pair] = lo;
                split2(acc[mt][nt][2] + bx, acc[mt][nt][3] + by, hi, lo);
                Cp[(size_t)(row+8)*512 + pair] = hi;
                Cp[(size_t)(row+8)*512 + 256 + pair] = lo;
            } else {
                int col = n0 + wn*32 + nt*8 + 2*lc;
                float bx = bias[col], by = bias[col + 1];
                *(float2*)(Cf + (size_t)row * Dm + col) =
                    make_float2(acc[mt][nt][0] + bx, acc[mt][nt][1] + by);
                *(float2*)(Cf + (size_t)(row + 8) * Dm + col) =
                    make_float2(acc[mt][nt][2] + bx, acc[mt][nt][3] + by);
            }
        }
    }
#undef A_LOADP
#undef B_LOADP
}

__global__ __launch_bounds__(128, 3) void qkv_pk()
{
    extern __shared__ uint32_t smu[];
    const int z = blockIdx.z;
    const int m0 = blockIdx.y * 128, n0 = blockIdx.x * 64;
    if (z == 0)
        pk_core<true, 0>(g_qdh, g_qdh, 256, 256, g_wqt, 512, nullptr, nullptr, g_q, m0, n0, smu);
    else if (z == 1)
        pk_core<true, 0>(g_kdh, g_kdh, 256, 256, g_wkt, 512, nullptr, nullptr, g_k, m0, n0, smu);
    else
        pk_core<false, 1>(g_vdb, g_vdb, 256, 256, g_wvt, 512, nullptr, g_vs, nullptr, m0, n0, smu);
}

__global__ __launch_bounds__(128, 3) void proj_pk(const float* __restrict__ bias)
{
    extern __shared__ uint32_t smu[];
    pk_core<false, 2>(g_ho, g_ho, 256, 256, g_pw, 512, bias, nullptr, g_po,
                      blockIdx.y * 128, blockIdx.x * 64, smu);
}

__global__ __launch_bounds__(128, 3) void lin_pk(const float* __restrict__ bias,
                                                 float* __restrict__ out)
{
    extern __shared__ uint32_t smu[];
    pk_core<false, 3>(g_qd, g_po, 256, 512, g_lw, 1024, bias, out, nullptr,
                      blockIdx.y * 128, blockIdx.x * 64, smu);
}

// ============================================================================
// QK^T (ldmatrix + fp16 HMMA) + softmax stats + dense attn fill, fused.
// CTA = (h, b, 128 q rows); 16 K-tiles of 64 rows. Single-barrier 2-stage
// pipeline per tile (wait0 -> sync -> prefetch t+1 -> compute t), same
// structure as pk_core. 3 CTAs/SM.
// ============================================================================
#define APADU 68
#define S_SMEM ((128*APADU + 2*64*APADU)*4 + 256*4*3)  /* 72704 */
__global__ __launch_bounds__(128, 3) void attn_stats_mma(float* __restrict__ attn)
{
    extern __shared__ uint32_t smu[];
    uint32_t* Qs = smu;
    uint32_t* Kbuf[2] = { smu + 128*APADU, smu + 128*APADU + 64*APADU };
    float* redm = (float*)(smu + 128*APADU + 2*64*APADU);
    float* reds = redm + 256;
    int*   redi = (int*)(reds + 256);

    const int tid = threadIdx.x;
    const int h = blockIdx.z, b = blockIdx.y, q0 = blockIdx.x * 128;
    const int wid = tid >> 5, lane = tid & 31;
    const int wm = wid & 1, wn = wid >> 1;
    const int lr = lane >> 2, lc = lane & 3;

    const uint32_t* Qg = g_q + ((size_t)(b * Ls + q0)) * 512 + h * 64;
    const uint32_t* Kg = g_k + ((size_t)(b * Ls)) * 512 + h * 64;
    const size_t rowbase = (size_t)(h * Bn + b) * Ls + q0;

    const int a_off = ((lane&7) + ((lane>>3)&1)*8)*APADU + (lane>>4)*4;
    const int b_off = (lane&7)*APADU + ((lane>>3)&1)*4 + (lane>>4)*32;
    const uint32_t qs_sh = smem_u32(Qs) + (wm*64*APADU + a_off)*4;
    uint32_t k_sh[2];
    k_sh[0] = smem_u32(Kbuf[0]) + (wn*32*APADU + b_off)*4;
    k_sh[1] = smem_u32(Kbuf[1]) + (wn*32*APADU + b_off)*4;

    // Q tile + K tile 0 in one cp.async group
#pragma unroll
    for (int i = 0; i < 16; i++) {
        int id = tid + i * 128;
        int row = id >> 4, seg = (id & 15) * 4;
        cp_async16(Qs + row*APADU + seg, Qg + (size_t)row * 512 + seg);
    }

#define K_LOAD(buf, t_) do {                                                    \
        _Pragma("unroll")                                                       \
        for (int i = 0; i < 8; i++) {                                           \
            int id = tid + i * 128;                                             \
            int row = id >> 4, seg = (id & 15) * 4;                             \
            cp_async16(Kbuf[buf] + row*APADU + seg,                             \
                       Kg + (size_t)((t_)*64 + row) * 512 + seg);               \
        }                                                                       \
    } while (0)

    K_LOAD(0, 0); CP_COMMIT();

    float rm[8], rs[8];
    int ridx[8];
#pragma unroll
    for (int i = 0; i < 8; i++) { rm[i] = -1e30f; rs[i] = 0.f; ridx[i] = 0; }

    int buf = 0;
    for (int t = 0; t < 16; t++) {
        CP_WAIT0();                 // tile t (and, at t=0, Q) complete
        __syncthreads();            // publish; all warps done reading buf^1
        if (t + 1 < 16) { K_LOAD(buf ^ 1, t + 1); CP_COMMIT(); }

        ACC_INIT()

#pragma unroll
        for (int ks = 0; ks < 4; ks++) {
            uint32_t bfr[4][4];
#pragma unroll
            for (int nt = 0; nt < 4; nt++)
                ldsm4(bfr[nt], k_sh[buf] + (nt*8*APADU + ks*8)*4);
#pragma unroll
            for (int mt = 0; mt < 4; mt++) {
                uint32_t ah[4], al[4];
                uint32_t aa = qs_sh + (mt*16*APADU + ks*8)*4;
                ldsm4(ah, aa);
                ldsm4(al, aa + 128);
#pragma unroll
                for (int nt = 0; nt < 4; nt++) {
                    mma16h(acc[mt][nt], ah, bfr[nt]);
                    mma16h(acc[mt][nt], ah, bfr[nt] + 2);
                    mma16h(acc[mt][nt], al, bfr[nt]);
                }
            }
        }

        // streaming zero-fill of this CTA's attn slice, s-range [t*64, t*64+64)
        {
            float4 z4 = make_float4(0.f, 0.f, 0.f, 0.f);
#pragma unroll
            for (int i = 0; i < 16; i++) {
                int id = tid + i * 128;
                int r = id >> 4, f4 = id & 15;
                __stcs((float4*)(attn + (rowbase + r) * Ls + t * 64 + f4 * 4), z4);
            }
        }

        // fold tile into per-thread stats (per-score predicated)
        const int sbase = t * 64 + wn * 32 + 2 * lc;
#pragma unroll
        for (int mt = 0; mt < 4; mt++) {
#pragma unroll
            for (int half = 0; half < 2; half++) {
                const int r8 = mt * 2 + half;
                float m = rm[r8], s_ = rs[r8];
                int id_ = ridx[r8];
#pragma unroll
                for (int nt = 0; nt < 4; nt++) {
#pragma unroll
                    for (int j = 0; j < 2; j++) {
                        float v = acc[mt][nt][half*2 + j];
                        if (v > m) { m = v; id_ = sbase + nt*8 + j; }
                        s_ += fex2(v * CCH);
                    }
                }
                rm[r8] = m; rs[r8] = s_; ridx[r8] = id_;
            }
        }
        buf ^= 1;
    }

    // quad reduce over lc
#pragma unroll
    for (int r8 = 0; r8 < 8; r8++) {
        float m = rm[r8], s_ = rs[r8];
        int id_ = ridx[r8];
#pragma unroll
        for (int off = 1; off <= 2; off <<= 1) {
            float om = __shfl_xor_sync(0xffffffffu, m, off);
            float os = __shfl_xor_sync(0xffffffffu, s_, off);
            int   oi = __shfl_xor_sync(0xffffffffu, id_, off);
            s_ += os;
            if (om > m) { m = om; id_ = oi; }
        }
        if (lc == 0) {
            int rowl = wm*64 + (r8 >> 1)*16 + (r8 & 1)*8 + lr;
            redm[rowl*2 + wn] = m;
            reds[rowl*2 + wn] = s_;
            redi[rowl*2 + wn] = id_;
        }
    }
    __syncthreads();

    {
        float m = redm[tid*2], s_ = reds[tid*2];
        int id_ = redi[tid*2];
        float om = redm[tid*2 + 1];
        s_ += reds[tid*2 + 1];
        if (om > m) { m = om; id_ = redi[tid*2 + 1]; }
        float p = fex2(m * CCH) / s_;
        int row = (int)(rowbase) + tid;
        g_p[row] = p;
        g_amax[row] = id_;
        attn[(rowbase + tid) * Ls + id_] = p;
    }
#undef K_LOAD
}

// ============================================================================
// attn @ V gather -> packed bf16 headout pairs (standalone, coalesced)
// ============================================================================
__global__ void gather_kernel()
{
    int idx4 = blockIdx.x * blockDim.x + threadIdx.x;
    if (idx4 >= M_ALL * Dm / 4) return;
    int e4 = idx4 & 15;
    int h  = (idx4 >> 4) & 7;
    int m  = idx4 >> 7;
    int b  = m >> 10;
    int q  = m & 1023;
    int row = (h * Bn + b) * Ls + q;
    float p = g_p[row];
    int   s = g_amax[row];
    float4 v = *(const float4*)(g_vs + ((size_t)(b * Ls + s)) * Dm + h * 64 + e4 * 4);
    uint32_t h0, l0, h1, l1;
    split2(v.x * p, v.y * p, h0, l0);
    split2(v.z * p, v.w * p, h1, l1);
    int pairbase = h * 32 + e4 * 2;
    *(uint2*)(g_ho + (size_t)m * 512 + pairbase)       = make_uint2(h0, h1);
    *(uint2*)(g_ho + (size_t)m * 512 + 256 + pairbase) = make_uint2(l0, l1);
}

// ============================================================================
extern "C" void kernel_launch(void* const* d_in, const int* in_sizes, int n_in,
                              void* d_out, int out_size)
{
    const float* q_data = (const float*)d_in[0];
    const float* k_data = (const float*)d_in[1];
    const float* v_data = (const float*)d_in[2];
    const float* w_qs   = (const float*)d_in[3];
    const float* w_ks   = (const float*)d_in[4];
    const float* w_vs   = (const float*)d_in[5];
    const float* proj_w = (const float*)d_in[6];
    const float* proj_b = (const float*)d_in[7];
    const float* lin_w  = (const float*)d_in[8];
    const float* lin_b  = (const float*)d_in[9];

    float* out  = (float*)d_out;                    // [B, L, D]
    float* attn = out + OUT_ELEMS;                  // [H*B, L, L]

    cudaFuncSetAttribute(qkv_pk,  cudaFuncAttributeMaxDynamicSharedMemorySize, PK_SMEM);
    cudaFuncSetAttribute(proj_pk, cudaFuncAttributeMaxDynamicSharedMemorySize, PK_SMEM);
    cudaFuncSetAttribute(lin_pk,  cudaFuncAttributeMaxDynamicSharedMemorySize, PK_SMEM);
    cudaFuncSetAttribute(attn_stats_mma, cudaFuncAttributeMaxDynamicSharedMemorySize, S_SMEM);

    // 0) pre-split all MMA inputs into packed-pair arrays
    prep_act<<<3 * M_ALL * 128 / 256, 256>>>(q_data, k_data, v_data);
    prep_w<<<(3*8*256*64 + 512*128 + 512*256 + 255) / 256, 256>>>(w_qs, w_ks, w_vs,
                                                                  proj_w, lin_w);

    // 1) Q/K/V projections (single-barrier 2-stage pipeline, 3 CTAs/SM)
    qkv_pk<<<dim3(8, 128, 3), 128, PK_SMEM>>>();

    // 2) QK^T + softmax stats + dense attn fill (single-barrier pipeline)
    attn_stats_mma<<<dim3(8, 16, 8), 128, S_SMEM>>>(attn);

    // 3) attn @ V gather -> packed bf16 headout
    gather_kernel<<<(M_ALL * Dm / 4 + 255) / 256, 256>>>();

    // 4) output projection -> packed bf16 projout
    proj_pk<<<dim3(8, 128), 128, PK_SMEM>>>(proj_b);

    // 5) final linear: out = [q_data | projout] @ lin_w^T + lin_b
    lin_pk<<<dim3(8, 128), 128, PK_SMEM>>>(lin_b, out);
}